// round 4
// baseline (speedup 1.0000x reference)
#include <cuda_runtime.h>
#include <cuda_bf16.h>

// AttWModel — N=1024, L=2048, D=128
// out[n] = sum_l softmax_l( X[n,l]·q[n] ) * ( X[n,l]·v ),  q[n] = W^T z[n]
//
// R4: split each n into SPLIT L-chunks for load balance (4096 uniform units
// over 148 SMs), partials merged by a tiny finalize kernel.

#define NB    1024
#define LSEQ  2048
#define DIM   128
#define NW    8
#define QGRP  8
#define SPLIT 4
#define ROWS_PER (LSEQ / SPLIT)   // 512

__device__ float g_q[NB * DIM];
__device__ float g_part[NB * SPLIT * 2];   // per unit: {Z, num}

// ---------------------------------------------------------------------------
// Kernel 1: q = W^T z, W staged in smem, QGRP n's per block.
// ---------------------------------------------------------------------------
__global__ void __launch_bounds__(256) compute_q_kernel(
    const float* __restrict__ z, const float* __restrict__ W)
{
    __shared__ __align__(16) float Ws[DIM * DIM];   // 64 KB
    __shared__ __align__(16) float zs[2 * DIM];

    const int tid = threadIdx.x;
    const int n0  = blockIdx.x * QGRP;

#pragma unroll
    for (int i = 0; i < (DIM * DIM) / (256 * 4); i++) {
        const int idx = (i * 256 + tid) * 4;
        reinterpret_cast<float4*>(Ws + idx)[0] =
            reinterpret_cast<const float4*>(W + idx)[0];
    }
    __syncthreads();

    const int d  = tid & (DIM - 1);
    const int ns = tid >> 7;

    for (int g = 0; g < QGRP; g += 2) {
        const int n = n0 + g + ns;
        if (tid < 2 * DIM) zs[tid] = z[(n0 + g) * DIM + tid];
        __syncthreads();

        const float* zrow = zs + ns * DIM;
        float a0 = 0.f, a1 = 0.f, a2 = 0.f, a3 = 0.f;
#pragma unroll
        for (int e = 0; e < DIM; e += 4) {
            a0 = fmaf(zrow[e + 0], Ws[(e + 0) * DIM + d], a0);
            a1 = fmaf(zrow[e + 1], Ws[(e + 1) * DIM + d], a1);
            a2 = fmaf(zrow[e + 2], Ws[(e + 2) * DIM + d], a2);
            a3 = fmaf(zrow[e + 3], Ws[(e + 3) * DIM + d], a3);
        }
        g_q[n * DIM + d] = (a0 + a1) + (a2 + a3);
        __syncthreads();
    }
}

// ---------------------------------------------------------------------------
// Kernel 2: streaming partials. One block per (n, L-chunk); 8 warps; 2-row
// unroll; score-only butterflies; deferred per-lane value accumulation;
// no max-subtraction; __expf; __ldcs streaming loads; pointer walking.
// ---------------------------------------------------------------------------
__global__ void __launch_bounds__(NW * 32, 8) attw_stream_kernel(
    const float* __restrict__ X,      // [NB, LSEQ, DIM]
    const float* __restrict__ v,      // [DIM]
    float* __restrict__ part)         // [NB*SPLIT*2]
{
    const int unit = blockIdx.x;
    const int n    = unit >> 2;          // / SPLIT
    const int s    = unit & (SPLIT - 1);
    const int lane = threadIdx.x & 31;
    const int wid  = threadIdx.x >> 5;

    const float4 q4 = reinterpret_cast<const float4*>(g_q + n * DIM)[lane];
    const float4 v4 = reinterpret_cast<const float4*>(v)[lane];

    const float4* Xp = reinterpret_cast<const float4*>(
        X + (size_t)n * LSEQ * DIM + (size_t)s * ROWS_PER * DIM)
        + (size_t)wid * 32 + lane;
    const float4* Xe = reinterpret_cast<const float4*>(
        X + (size_t)n * LSEQ * DIM + (size_t)(s + 1) * ROWS_PER * DIM);

    float Z = 0.f, num = 0.f;

#pragma unroll 1
    for (; Xp < Xe; Xp += 2 * NW * 32) {
        const float4 x0 = __ldcs(Xp);
        const float4 x1 = __ldcs(Xp + NW * 32);

        float s0 = x0.x*q4.x + x0.y*q4.y + x0.z*q4.z + x0.w*q4.w;
        float t0 = x0.x*v4.x + x0.y*v4.y + x0.z*v4.z + x0.w*v4.w;
        float s1 = x1.x*q4.x + x1.y*q4.y + x1.z*q4.z + x1.w*q4.w;
        float t1 = x1.x*v4.x + x1.y*v4.y + x1.z*v4.z + x1.w*v4.w;

#pragma unroll
        for (int off = 16; off > 0; off >>= 1) {
            s0 += __shfl_xor_sync(0xffffffffu, s0, off);
            s1 += __shfl_xor_sync(0xffffffffu, s1, off);
        }

        const float p0 = __expf(s0);
        const float p1 = __expf(s1);
        Z   += p0 + p1;
        num  = fmaf(p0, t0, fmaf(p1, t1, num));
    }

#pragma unroll
    for (int off = 16; off > 0; off >>= 1)
        num += __shfl_xor_sync(0xffffffffu, num, off);

    __shared__ float sZ[NW], sN[NW];
    if (lane == 0) { sZ[wid] = Z; sN[wid] = num; }
    __syncthreads();

    if (threadIdx.x == 0) {
        float Zt = 0.f, Nt = 0.f;
#pragma unroll
        for (int w = 0; w < NW; w++) { Zt += sZ[w]; Nt += sN[w]; }
        part[unit * 2]     = Zt;
        part[unit * 2 + 1] = Nt;
    }
}

// ---------------------------------------------------------------------------
// Kernel 3: finalize. out[n] = (sum_s num) / (sum_s Z)
// ---------------------------------------------------------------------------
__global__ void __launch_bounds__(256) finalize_kernel(
    const float* __restrict__ part, float* __restrict__ out)
{
    const int n = blockIdx.x * 256 + threadIdx.x;
    if (n < NB) {
        const float* p = part + n * SPLIT * 2;
        float Zt = 0.f, Nt = 0.f;
#pragma unroll
        for (int sIdx = 0; sIdx < SPLIT; sIdx++) {
            Zt += p[sIdx * 2];
            Nt += p[sIdx * 2 + 1];
        }
        out[n] = Nt / Zt;
    }
}

extern "C" void kernel_launch(void* const* d_in, const int* in_sizes, int n_in,
                              void* d_out, int out_size)
{
    const float* X = (const float*)d_in[0];
    const float* z = (const float*)d_in[1];
    const float* W = (const float*)d_in[2];
    const float* v = (const float*)d_in[3];
    float* out = (float*)d_out;

    float* part;
    cudaGetSymbolAddress((void**)&part, g_part);

    compute_q_kernel<<<NB / QGRP, 256>>>(z, W);
    attw_stream_kernel<<<NB * SPLIT, NW * 32>>>(X, v, part);
    finalize_kernel<<<(NB + 255) / 256, 256>>>(part, out);
}